// round 2
// baseline (speedup 1.0000x reference)
#include <cuda_runtime.h>

#define NX 1000

// ---------------- device-global scratch (no allocations allowed) ------------
__device__ unsigned int g_min_bits;
__device__ unsigned int g_max_bits;
__device__ unsigned int g_hist[2][NX];

// Order-preserving float <-> uint encoding (monotone for all finite floats)
__device__ __forceinline__ unsigned int enc_f(float f) {
    unsigned int u = __float_as_uint(f);
    return (u & 0x80000000u) ? ~u : (u | 0x80000000u);
}
__device__ __forceinline__ float dec_f(unsigned int u) {
    u = (u & 0x80000000u) ? (u & 0x7FFFFFFFu) : ~u;
    return __uint_as_float(u);
}

// The linspace grid point, matching f32 "lo + j*step" with exact endpoint.
__device__ __forceinline__ float xval(int j, float lo, float hi, float step) {
    return (j >= NX - 1) ? hi : fmaf((float)j, step, lo);
}

// ---------------- kernel 0: reset state (graph replays!) --------------------
__global__ void init_k() {
    int i = blockIdx.x * blockDim.x + threadIdx.x;
    if (i < 2 * NX) ((unsigned int*)g_hist)[i] = 0u;
    if (i == 0) { g_min_bits = 0xFFFFFFFFu; g_max_bits = 0u; }
}

// ---------------- kernel 1: global min/max over both arrays -----------------
__global__ void minmax_k(const float* __restrict__ a,
                         const float* __restrict__ b, int n) {
    int n4 = n >> 2;
    const float4* __restrict__ a4 = (const float4*)a;
    const float4* __restrict__ b4 = (const float4*)b;
    unsigned int mn = 0xFFFFFFFFu, mx = 0u;
    int stride = gridDim.x * blockDim.x;
    for (int i = blockIdx.x * blockDim.x + threadIdx.x; i < n4; i += stride) {
        float4 va = a4[i];
        float4 vb = b4[i];
        unsigned int e;
        e = enc_f(va.x); mn = min(mn, e); mx = max(mx, e);
        e = enc_f(va.y); mn = min(mn, e); mx = max(mx, e);
        e = enc_f(va.z); mn = min(mn, e); mx = max(mx, e);
        e = enc_f(va.w); mn = min(mn, e); mx = max(mx, e);
        e = enc_f(vb.x); mn = min(mn, e); mx = max(mx, e);
        e = enc_f(vb.y); mn = min(mn, e); mx = max(mx, e);
        e = enc_f(vb.z); mn = min(mn, e); mx = max(mx, e);
        e = enc_f(vb.w); mn = min(mn, e); mx = max(mx, e);
    }
    // scalar tail (n not divisible by 4 — not the case here, but be safe)
    if (blockIdx.x == 0 && threadIdx.x == 0) {
        for (int i = (n4 << 2); i < n; ++i) {
            unsigned int e = enc_f(a[i]); mn = min(mn, e); mx = max(mx, e);
            e = enc_f(b[i]); mn = min(mn, e); mx = max(mx, e);
        }
    }
    // warp reduce
    for (int o = 16; o; o >>= 1) {
        mn = min(mn, __shfl_xor_sync(0xFFFFFFFFu, mn, o));
        mx = max(mx, __shfl_xor_sync(0xFFFFFFFFu, mx, o));
    }
    __shared__ unsigned int smn[32], smx[32];
    int lane = threadIdx.x & 31, w = threadIdx.x >> 5;
    if (lane == 0) { smn[w] = mn; smx[w] = mx; }
    __syncthreads();
    if (threadIdx.x < 32) {
        int nw = blockDim.x >> 5;
        mn = (threadIdx.x < nw) ? smn[threadIdx.x] : 0xFFFFFFFFu;
        mx = (threadIdx.x < nw) ? smx[threadIdx.x] : 0u;
        for (int o = 16; o; o >>= 1) {
            mn = min(mn, __shfl_xor_sync(0xFFFFFFFFu, mn, o));
            mx = max(mx, __shfl_xor_sync(0xFFFFFFFFu, mx, o));
        }
        if (threadIdx.x == 0) {
            atomicMin(&g_min_bits, mn);
            atomicMax(&g_max_bits, mx);
        }
    }
}

// first grid index j with x_j >= v  (exact w.r.t. our xval formula)
__device__ __forceinline__ int binof(float v, float lo, float hi,
                                     float step, float invstep) {
    if (!(step > 0.0f)) return 0;
    float f = (v - lo) * invstep;
    int j = (int)ceilf(f);
    j = max(0, min(j, NX - 1));
    while (j < NX - 1 && xval(j, lo, hi, step) < v) ++j;
    while (j > 0 && xval(j - 1, lo, hi, step) >= v) --j;
    return j;
}

// ---------------- kernel 2: 2x 1000-bin histograms --------------------------
__global__ void hist_k(const float* __restrict__ a,
                       const float* __restrict__ b, int n) {
    __shared__ unsigned int sh[2][NX];
    for (int i = threadIdx.x; i < 2 * NX; i += blockDim.x)
        ((unsigned int*)sh)[i] = 0u;
    __syncthreads();

    float lo = dec_f(g_min_bits);
    float hi = dec_f(g_max_bits);
    float step = (hi - lo) / (float)(NX - 1);
    float invstep = (step > 0.0f) ? (1.0f / step) : 0.0f;

    int n4 = n >> 2;
    const float4* __restrict__ a4 = (const float4*)a;
    const float4* __restrict__ b4 = (const float4*)b;
    int stride = gridDim.x * blockDim.x;
    for (int i = blockIdx.x * blockDim.x + threadIdx.x; i < n4; i += stride) {
        float4 va = a4[i];
        float4 vb = b4[i];
        atomicAdd(&sh[0][binof(va.x, lo, hi, step, invstep)], 1u);
        atomicAdd(&sh[0][binof(va.y, lo, hi, step, invstep)], 1u);
        atomicAdd(&sh[0][binof(va.z, lo, hi, step, invstep)], 1u);
        atomicAdd(&sh[0][binof(va.w, lo, hi, step, invstep)], 1u);
        atomicAdd(&sh[1][binof(vb.x, lo, hi, step, invstep)], 1u);
        atomicAdd(&sh[1][binof(vb.y, lo, hi, step, invstep)], 1u);
        atomicAdd(&sh[1][binof(vb.z, lo, hi, step, invstep)], 1u);
        atomicAdd(&sh[1][binof(vb.w, lo, hi, step, invstep)], 1u);
    }
    if (blockIdx.x == 0 && threadIdx.x == 0) {
        for (int i = (n4 << 2); i < n; ++i) {
            atomicAdd(&sh[0][binof(a[i], lo, hi, step, invstep)], 1u);
            atomicAdd(&sh[1][binof(b[i], lo, hi, step, invstep)], 1u);
        }
    }
    __syncthreads();
    for (int i = threadIdx.x; i < NX; i += blockDim.x) {
        unsigned int c0 = sh[0][i];
        unsigned int c1 = sh[1][i];
        if (c0) atomicAdd(&g_hist[0][i], c0);
        if (c1) atomicAdd(&g_hist[1][i], c1);
    }
}

// ---------------- kernel 3: scan + trapz (single block) ---------------------
__global__ void finish_k(float* __restrict__ out, int n) {
    __shared__ unsigned int s0[1024];
    __shared__ unsigned int s1[1024];
    int t = threadIdx.x;
    s0[t] = (t < NX) ? g_hist[0][t] : 0u;
    s1[t] = (t < NX) ? g_hist[1][t] : 0u;
    __syncthreads();
    // Hillis-Steele inclusive scan over 1024 slots
    for (int off = 1; off < 1024; off <<= 1) {
        unsigned int v0 = (t >= off) ? s0[t - off] : 0u;
        unsigned int v1 = (t >= off) ? s1[t - off] : 0u;
        __syncthreads();
        s0[t] += v0;
        s1[t] += v1;
        __syncthreads();
    }

    float lo = dec_f(g_min_bits);
    float hi = dec_f(g_max_bits);
    float step = (hi - lo) / (float)(NX - 1);
    float nf = (float)n;

    double acc = 0.0;
    if (t < NX - 1) {
        // replicate reference's f32 rounding per term
        float cp0 = (float)s0[t] / nf;
        float ct0 = (float)s1[t] / nf;
        float cp1 = (float)s0[t + 1] / nf;
        float ct1 = (float)s1[t + 1] / nf;
        float y0 = cp0 - ct0; y0 = y0 * y0;
        float y1 = cp1 - ct1; y1 = y1 * y1;
        float dx = xval(t + 1, lo, hi, step) - xval(t, lo, hi, step);
        acc = (double)(0.5f * (y0 + y1) * dx);
    }
    // block reduce (doubles)
    for (int o = 16; o; o >>= 1)
        acc += __shfl_xor_sync(0xFFFFFFFFu, acc, o);
    __shared__ double sd[32];
    int lane = t & 31, w = t >> 5;
    if (lane == 0) sd[w] = acc;
    __syncthreads();
    if (t < 32) {
        acc = (t < 32) ? sd[t] : 0.0;
        for (int o = 16; o; o >>= 1)
            acc += __shfl_xor_sync(0xFFFFFFFFu, acc, o);
        if (t == 0) out[0] = (float)acc;
    }
}

// ---------------- launch ----------------------------------------------------
extern "C" void kernel_launch(void* const* d_in, const int* in_sizes, int n_in,
                              void* d_out, int out_size) {
    const float* p = (const float*)d_in[0];
    const float* tg = (const float*)d_in[1];
    int n = in_sizes[0];

    init_k<<<2, 1024>>>();
    minmax_k<<<1184, 256>>>(p, tg, n);
    hist_k<<<1184, 256>>>(p, tg, n);
    finish_k<<<1, 1024>>>((float*)d_out, n);
}

// round 3
// speedup vs baseline: 1.1635x; 1.1635x over previous
#include <cuda_runtime.h>
#include <math_constants.h>

#define NX 1000

// ---------------- device-global scratch (zero-init is the neutral state) ----
__device__ unsigned int g_negmin_bits;   // holds max(~enc(v))  -> min value
__device__ unsigned int g_max_bits;      // holds max( enc(v))  -> max value
__device__ unsigned int g_hist[2][NX];

// Order-preserving float <-> uint encoding (monotone for all finite floats)
__device__ __forceinline__ unsigned int enc_f(float f) {
    unsigned int u = __float_as_uint(f);
    return (u & 0x80000000u) ? ~u : (u | 0x80000000u);
}
__device__ __forceinline__ float dec_f(unsigned int u) {
    u = (u & 0x80000000u) ? (u & 0x7FFFFFFFu) : ~u;
    return __uint_as_float(u);
}

// The linspace grid point, matching f32 "lo + j*step" with exact endpoint.
__device__ __forceinline__ float xval(int j, float lo, float hi, float step) {
    return (j >= NX - 1) ? hi : fmaf((float)j, step, lo);
}

// ---------------- kernel 1: global min/max over both arrays -----------------
__global__ void minmax_k(const float* __restrict__ a,
                         const float* __restrict__ b, int n) {
    int n4 = n >> 2;
    const float4* __restrict__ a4 = (const float4*)a;
    const float4* __restrict__ b4 = (const float4*)b;
    float mn = CUDART_INF_F, mx = -CUDART_INF_F;
    int S = gridDim.x * blockDim.x;
    int i = blockIdx.x * blockDim.x + threadIdx.x;
    // 2-way unroll: 4 independent LDG.128 in flight per iteration
    for (; i + S < n4; i += 2 * S) {
        float4 v0 = a4[i];
        float4 v1 = a4[i + S];
        float4 w0 = b4[i];
        float4 w1 = b4[i + S];
        mn = fminf(mn, fminf(fminf(v0.x, v0.y), fminf(v0.z, v0.w)));
        mx = fmaxf(mx, fmaxf(fmaxf(v0.x, v0.y), fmaxf(v0.z, v0.w)));
        mn = fminf(mn, fminf(fminf(v1.x, v1.y), fminf(v1.z, v1.w)));
        mx = fmaxf(mx, fmaxf(fmaxf(v1.x, v1.y), fmaxf(v1.z, v1.w)));
        mn = fminf(mn, fminf(fminf(w0.x, w0.y), fminf(w0.z, w0.w)));
        mx = fmaxf(mx, fmaxf(fmaxf(w0.x, w0.y), fmaxf(w0.z, w0.w)));
        mn = fminf(mn, fminf(fminf(w1.x, w1.y), fminf(w1.z, w1.w)));
        mx = fmaxf(mx, fmaxf(fmaxf(w1.x, w1.y), fmaxf(w1.z, w1.w)));
    }
    for (; i < n4; i += S) {
        float4 v0 = a4[i];
        float4 w0 = b4[i];
        mn = fminf(mn, fminf(fminf(v0.x, v0.y), fminf(v0.z, v0.w)));
        mx = fmaxf(mx, fmaxf(fmaxf(v0.x, v0.y), fmaxf(v0.z, v0.w)));
        mn = fminf(mn, fminf(fminf(w0.x, w0.y), fminf(w0.z, w0.w)));
        mx = fmaxf(mx, fmaxf(fmaxf(w0.x, w0.y), fmaxf(w0.z, w0.w)));
    }
    if (blockIdx.x == 0 && threadIdx.x == 0) {   // scalar tail (n % 4)
        for (int k = (n4 << 2); k < n; ++k) {
            mn = fminf(mn, fminf(a[k], b[k]));
            mx = fmaxf(mx, fmaxf(a[k], b[k]));
        }
    }
    // warp reduce
    for (int o = 16; o; o >>= 1) {
        mn = fminf(mn, __shfl_xor_sync(0xFFFFFFFFu, mn, o));
        mx = fmaxf(mx, __shfl_xor_sync(0xFFFFFFFFu, mx, o));
    }
    __shared__ float smn[32], smx[32];
    int lane = threadIdx.x & 31, w = threadIdx.x >> 5;
    if (lane == 0) { smn[w] = mn; smx[w] = mx; }
    __syncthreads();
    if (threadIdx.x < 32) {
        int nw = blockDim.x >> 5;
        mn = (threadIdx.x < nw) ? smn[threadIdx.x] : CUDART_INF_F;
        mx = (threadIdx.x < nw) ? smx[threadIdx.x] : -CUDART_INF_F;
        for (int o = 16; o; o >>= 1) {
            mn = fminf(mn, __shfl_xor_sync(0xFFFFFFFFu, mn, o));
            mx = fmaxf(mx, __shfl_xor_sync(0xFFFFFFFFu, mx, o));
        }
        if (threadIdx.x == 0) {
            atomicMax(&g_negmin_bits, ~enc_f(mn));
            atomicMax(&g_max_bits, enc_f(mx));
        }
    }
}

// first grid index j with x_j >= v  (exact w.r.t. our xval formula)
__device__ __forceinline__ int binof(float v, float lo, float hi,
                                     float step, float invstep) {
    if (!(step > 0.0f)) return 0;
    float f = (v - lo) * invstep;
    int j = (int)ceilf(f);
    j = max(0, min(j, NX - 1));
    while (j < NX - 1 && xval(j, lo, hi, step) < v) ++j;
    while (j > 0 && xval(j - 1, lo, hi, step) >= v) --j;
    return j;
}

// ---------------- kernel 2: 2x 1000-bin histograms --------------------------
__global__ void hist_k(const float* __restrict__ a,
                       const float* __restrict__ b, int n) {
    __shared__ unsigned int sh[2][NX];
    for (int i = threadIdx.x; i < 2 * NX; i += blockDim.x)
        ((unsigned int*)sh)[i] = 0u;
    __syncthreads();

    float lo = dec_f(~g_negmin_bits);
    float hi = dec_f(g_max_bits);
    float step = (hi - lo) / (float)(NX - 1);
    float invstep = (step > 0.0f) ? (1.0f / step) : 0.0f;

    int n4 = n >> 2;
    const float4* __restrict__ a4 = (const float4*)a;
    const float4* __restrict__ b4 = (const float4*)b;
    int S = gridDim.x * blockDim.x;
    int i = blockIdx.x * blockDim.x + threadIdx.x;
    for (; i + S < n4; i += 2 * S) {
        float4 v0 = a4[i];
        float4 v1 = a4[i + S];
        float4 w0 = b4[i];
        float4 w1 = b4[i + S];
        atomicAdd(&sh[0][binof(v0.x, lo, hi, step, invstep)], 1u);
        atomicAdd(&sh[0][binof(v0.y, lo, hi, step, invstep)], 1u);
        atomicAdd(&sh[0][binof(v0.z, lo, hi, step, invstep)], 1u);
        atomicAdd(&sh[0][binof(v0.w, lo, hi, step, invstep)], 1u);
        atomicAdd(&sh[0][binof(v1.x, lo, hi, step, invstep)], 1u);
        atomicAdd(&sh[0][binof(v1.y, lo, hi, step, invstep)], 1u);
        atomicAdd(&sh[0][binof(v1.z, lo, hi, step, invstep)], 1u);
        atomicAdd(&sh[0][binof(v1.w, lo, hi, step, invstep)], 1u);
        atomicAdd(&sh[1][binof(w0.x, lo, hi, step, invstep)], 1u);
        atomicAdd(&sh[1][binof(w0.y, lo, hi, step, invstep)], 1u);
        atomicAdd(&sh[1][binof(w0.z, lo, hi, step, invstep)], 1u);
        atomicAdd(&sh[1][binof(w0.w, lo, hi, step, invstep)], 1u);
        atomicAdd(&sh[1][binof(w1.x, lo, hi, step, invstep)], 1u);
        atomicAdd(&sh[1][binof(w1.y, lo, hi, step, invstep)], 1u);
        atomicAdd(&sh[1][binof(w1.z, lo, hi, step, invstep)], 1u);
        atomicAdd(&sh[1][binof(w1.w, lo, hi, step, invstep)], 1u);
    }
    for (; i < n4; i += S) {
        float4 v0 = a4[i];
        float4 w0 = b4[i];
        atomicAdd(&sh[0][binof(v0.x, lo, hi, step, invstep)], 1u);
        atomicAdd(&sh[0][binof(v0.y, lo, hi, step, invstep)], 1u);
        atomicAdd(&sh[0][binof(v0.z, lo, hi, step, invstep)], 1u);
        atomicAdd(&sh[0][binof(v0.w, lo, hi, step, invstep)], 1u);
        atomicAdd(&sh[1][binof(w0.x, lo, hi, step, invstep)], 1u);
        atomicAdd(&sh[1][binof(w0.y, lo, hi, step, invstep)], 1u);
        atomicAdd(&sh[1][binof(w0.z, lo, hi, step, invstep)], 1u);
        atomicAdd(&sh[1][binof(w0.w, lo, hi, step, invstep)], 1u);
    }
    if (blockIdx.x == 0 && threadIdx.x == 0) {   // scalar tail
        for (int k = (n4 << 2); k < n; ++k) {
            atomicAdd(&sh[0][binof(a[k], lo, hi, step, invstep)], 1u);
            atomicAdd(&sh[1][binof(b[k], lo, hi, step, invstep)], 1u);
        }
    }
    __syncthreads();
    for (int i2 = threadIdx.x; i2 < NX; i2 += blockDim.x) {
        unsigned int c0 = sh[0][i2];
        unsigned int c1 = sh[1][i2];
        if (c0) atomicAdd(&g_hist[0][i2], c0);
        if (c1) atomicAdd(&g_hist[1][i2], c1);
    }
}

// ---------------- kernel 3: scan + trapz + STATE RESET (single block) -------
__global__ void finish_k(float* __restrict__ out, int n) {
    int t = threadIdx.x;
    int lane = t & 31, w = t >> 5;

    float lo = dec_f(~g_negmin_bits);
    float hi = dec_f(g_max_bits);
    float step = (hi - lo) / (float)(NX - 1);

    unsigned int s0 = (t < NX) ? g_hist[0][t] : 0u;
    unsigned int s1 = (t < NX) ? g_hist[1][t] : 0u;

    // warp inclusive scan
    #pragma unroll
    for (int o = 1; o < 32; o <<= 1) {
        unsigned int u0 = __shfl_up_sync(0xFFFFFFFFu, s0, o);
        unsigned int u1 = __shfl_up_sync(0xFFFFFFFFu, s1, o);
        if (lane >= o) { s0 += u0; s1 += u1; }
    }
    __shared__ unsigned int ws0[32], ws1[32];
    if (lane == 31) { ws0[w] = s0; ws1[w] = s1; }
    __syncthreads();
    if (w == 0) {   // scan the 32 warp sums
        unsigned int a0 = ws0[lane], a1 = ws1[lane];
        #pragma unroll
        for (int o = 1; o < 32; o <<= 1) {
            unsigned int u0 = __shfl_up_sync(0xFFFFFFFFu, a0, o);
            unsigned int u1 = __shfl_up_sync(0xFFFFFFFFu, a1, o);
            if (lane >= o) { a0 += u0; a1 += u1; }
        }
        ws0[lane] = a0; ws1[lane] = a1;
    }
    __syncthreads();
    if (w > 0) { s0 += ws0[w - 1]; s1 += ws1[w - 1]; }

    __shared__ unsigned int sc0[1024], sc1[1024];
    sc0[t] = s0; sc1[t] = s1;
    __syncthreads();

    float nf = (float)n;
    double acc = 0.0;
    if (t < NX - 1) {
        // replicate reference's f32 rounding per term
        float cp0 = (float)sc0[t] / nf;
        float ct0 = (float)sc1[t] / nf;
        float cp1 = (float)sc0[t + 1] / nf;
        float ct1 = (float)sc1[t + 1] / nf;
        float y0 = cp0 - ct0; y0 = y0 * y0;
        float y1 = cp1 - ct1; y1 = y1 * y1;
        float dx = xval(t + 1, lo, hi, step) - xval(t, lo, hi, step);
        acc = (double)(0.5f * (y0 + y1) * dx);
    }
    // block reduce doubles
    for (int o = 16; o; o >>= 1)
        acc += __shfl_xor_sync(0xFFFFFFFFu, acc, o);
    __shared__ double sd[32];
    if (lane == 0) sd[w] = acc;
    __syncthreads();
    if (t < 32) {
        acc = sd[t];
        for (int o = 16; o; o >>= 1)
            acc += __shfl_xor_sync(0xFFFFFFFFu, acc, o);
        if (t == 0) out[0] = (float)acc;
    }

    // ---- reset all device state for the next graph replay ----
    __syncthreads();
    for (int i = t; i < 2 * NX; i += 1024)
        ((unsigned int*)g_hist)[i] = 0u;
    if (t == 0) { g_negmin_bits = 0u; g_max_bits = 0u; }
}

// ---------------- launch ----------------------------------------------------
extern "C" void kernel_launch(void* const* d_in, const int* in_sizes, int n_in,
                              void* d_out, int out_size) {
    const float* p = (const float*)d_in[0];
    const float* tg = (const float*)d_in[1];
    int n = in_sizes[0];

    minmax_k<<<1184, 256>>>(p, tg, n);
    hist_k<<<1184, 256>>>(p, tg, n);
    finish_k<<<1, 1024>>>((float*)d_out, n);
}